// round 3
// baseline (speedup 1.0000x reference)
#include <cuda_runtime.h>
#include <math.h>

#define NCLS 19
#define DD   128
#define HWP  65536          // H*W
#define BB   8
#define NPIX (BB*HWP)       // 524288

// ---- static scratch (no allocations allowed) ----
__device__ float          g_sums[NCLS*DD];
__device__ float          g_means[NCLS*DD];
__device__ int            g_cnt[NCLS];
__device__ float          g_var[NCLS];
__device__ unsigned char  g_labs[NPIX];

// ---------------------------------------------------------------- zero
__global__ void k_zero() {
    int t = blockIdx.x*blockDim.x + threadIdx.x;
    if (t < NCLS*DD) g_sums[t] = 0.f;
    if (t < NCLS) { g_cnt[t] = 0; g_var[t] = 0.f; }
}

// ------------------------------------------------------ label pack + hist
__global__ void __launch_bounds__(256) k_prep(const int* __restrict__ labels) {
    __shared__ int hist[NCLS];
    int t = threadIdx.x;
    if (t < NCLS) hist[t] = 0;
    __syncthreads();
    int p = blockIdx.x*256 + t;
    int lab = labels[p];
    unsigned char u = (lab >= 0 && lab < NCLS) ? (unsigned char)lab : (unsigned char)255;
    g_labs[p] = u;
    if (u < NCLS) atomicAdd(&hist[u], 1);
    __syncthreads();
    if (t < NCLS) atomicAdd(&g_cnt[t], hist[t]);
}

// ---------------------------------------------------------------- pass 1
// Each thread owns a fixed d-quad (d0..d0+3). One label test guards TWO
// packed f32x2 adds (4 elements): 14.25 instrs/element. Non-volatile asm
// lets ptxas pipeline the 19 independent class chains.
__device__ __forceinline__ unsigned long long packf2(float lo, float hi) {
    unsigned long long v;
    asm("mov.b64 %0, {%1, %2};" : "=l"(v) : "f"(lo), "f"(hi));
    return v;
}

template<int CI>
__device__ __forceinline__ void step_all(unsigned long long* accA, unsigned long long* accB,
                                         unsigned long long vA, unsigned long long vB, int lab) {
    asm("{\n\t.reg .pred p;\n\t"
        "setp.eq.s32 p, %2, %3;\n\t"
        "@p add.rn.f32x2 %0, %0, %4;\n\t"
        "@p add.rn.f32x2 %1, %1, %5;\n\t}"
        : "+l"(accA[CI]), "+l"(accB[CI])
        : "r"(lab), "n"(CI), "l"(vA), "l"(vB));
    if constexpr (CI + 1 < NCLS) step_all<CI+1>(accA, accB, vA, vB, lab);
}

#define P1_SPLIT 4
#define P1_THREADS 128

__global__ void __launch_bounds__(P1_THREADS) k_pass1(const float* __restrict__ feats) {
    int jq = blockIdx.x;            // d-quad index 0..31
    int b  = blockIdx.y;            // batch plane 0..7
    int s  = blockIdx.z;            // pixel split 0..3
    int d0 = jq * 4;
    const int nvec  = HWP / 4;          // 16384 float4 per plane
    const int chunk = nvec / P1_SPLIT;  // 4096
    const int base  = s * chunk;

    const float4* f0 = (const float4*)(feats + ((size_t)b*DD + d0    ) * HWP) + base;
    const float4* f1 = (const float4*)(feats + ((size_t)b*DD + d0 + 1) * HWP) + base;
    const float4* f2 = (const float4*)(feats + ((size_t)b*DD + d0 + 2) * HWP) + base;
    const float4* f3 = (const float4*)(feats + ((size_t)b*DD + d0 + 3) * HWP) + base;
    const uchar4* lb = (const uchar4*)(g_labs + (size_t)b*HWP) + base;

    unsigned long long accA[NCLS], accB[NCLS];
    #pragma unroll
    for (int c = 0; c < NCLS; c++) { accA[c] = 0ull; accB[c] = 0ull; }

    for (int i = threadIdx.x; i < chunk; i += P1_THREADS) {
        float4 a0 = f0[i];
        float4 a1 = f1[i];
        float4 a2 = f2[i];
        float4 a3 = f3[i];
        uchar4 l  = lb[i];
        step_all<0>(accA, accB, packf2(a0.x, a1.x), packf2(a2.x, a3.x), (int)l.x);
        step_all<0>(accA, accB, packf2(a0.y, a1.y), packf2(a2.y, a3.y), (int)l.y);
        step_all<0>(accA, accB, packf2(a0.z, a1.z), packf2(a2.z, a3.z), (int)l.z);
        step_all<0>(accA, accB, packf2(a0.w, a1.w), packf2(a2.w, a3.w), (int)l.w);
    }

    // block reduce: warp shuffle -> shared atomics -> global atomics
    __shared__ float shred[NCLS*4];
    if (threadIdx.x < NCLS*4) shred[threadIdx.x] = 0.f;
    __syncthreads();
    int lane = threadIdx.x & 31;
    #pragma unroll
    for (int c = 0; c < NCLS; c++) {
        float x0, x1, x2, x3;
        asm("mov.b64 {%0, %1}, %2;" : "=f"(x0), "=f"(x1) : "l"(accA[c]));
        asm("mov.b64 {%0, %1}, %2;" : "=f"(x2), "=f"(x3) : "l"(accB[c]));
        #pragma unroll
        for (int o = 16; o; o >>= 1) {
            x0 += __shfl_down_sync(0xffffffffu, x0, o);
            x1 += __shfl_down_sync(0xffffffffu, x1, o);
            x2 += __shfl_down_sync(0xffffffffu, x2, o);
            x3 += __shfl_down_sync(0xffffffffu, x3, o);
        }
        if (lane == 0) {
            atomicAdd(&shred[c*4+0], x0);
            atomicAdd(&shred[c*4+1], x1);
            atomicAdd(&shred[c*4+2], x2);
            atomicAdd(&shred[c*4+3], x3);
        }
    }
    __syncthreads();
    if (threadIdx.x < NCLS*4) {
        int c = threadIdx.x >> 2, k = threadIdx.x & 3;
        atomicAdd(&g_sums[c*DD + d0 + k], shred[threadIdx.x]);
    }
}

// ---------------------------------------------------------------- means
__global__ void k_means() {
    int t = blockIdx.x*blockDim.x + threadIdx.x;
    if (t < NCLS*DD) {
        int c = t >> 7;
        g_means[t] = g_sums[t] / fmaxf((float)g_cnt[c], 1.f);
    }
}

// ---------------------------------------------------------------- pass 2
// Each thread owns 4 pixels via float4 loads (LDG.128). Means in shared at
// stride 129 -> conflict-free LDS for arbitrary label mixes.
__global__ void __launch_bounds__(256) k_pass2(const float* __restrict__ feats) {
    __shared__ float ms[NCLS*129];
    __shared__ float vs[NCLS];
    int t = threadIdx.x;
    for (int i = t; i < NCLS*DD; i += 256)
        ms[(i >> 7)*129 + (i & 127)] = g_means[i];
    if (t < NCLS) vs[t] = 0.f;
    __syncthreads();

    int q  = blockIdx.x*256 + t;      // pixel-quad index
    int b  = q >> 14;                 // 16384 quads per batch plane
    int hq = q & 16383;
    const float4* fp = (const float4*)(feats + (size_t)b*DD*HWP) + hq;
    uchar4 l = ((const uchar4*)g_labs)[q];

    int l0 = l.x, l1 = l.y, l2 = l.z, l3 = l.w;
    const float* m0 = ms + (l0 < NCLS ? l0 : 0)*129;
    const float* m1 = ms + (l1 < NCLS ? l1 : 0)*129;
    const float* m2 = ms + (l2 < NCLS ? l2 : 0)*129;
    const float* m3 = ms + (l3 < NCLS ? l3 : 0)*129;

    float acc0 = 0.f, acc1 = 0.f, acc2 = 0.f, acc3 = 0.f;
    #pragma unroll 8
    for (int d = 0; d < DD; d++) {
        float4 v = fp[(size_t)d * (HWP/4)];
        float df;
        df = v.x - m0[d]; acc0 = fmaf(df, df, acc0);
        df = v.y - m1[d]; acc1 = fmaf(df, df, acc1);
        df = v.z - m2[d]; acc2 = fmaf(df, df, acc2);
        df = v.w - m3[d]; acc3 = fmaf(df, df, acc3);
    }
    if (l0 < NCLS) { float h = fmaxf(sqrtf(acc0) - 0.5f, 0.f); atomicAdd(&vs[l0], h*h); }
    if (l1 < NCLS) { float h = fmaxf(sqrtf(acc1) - 0.5f, 0.f); atomicAdd(&vs[l1], h*h); }
    if (l2 < NCLS) { float h = fmaxf(sqrtf(acc2) - 0.5f, 0.f); atomicAdd(&vs[l2], h*h); }
    if (l3 < NCLS) { float h = fmaxf(sqrtf(acc3) - 0.5f, 0.f); atomicAdd(&vs[l3], h*h); }
    __syncthreads();
    if (t < NCLS) atomicAdd(&g_var[t], vs[t]);
}

// ---------------------------------------------------------------- final
__global__ void __launch_bounds__(512) k_final(float* __restrict__ out) {
    __shared__ float vld[NCLS];
    __shared__ float sreg[NCLS];
    __shared__ float spair[NCLS*NCLS];
    int t = threadIdx.x;
    if (t < NCLS) vld[t] = (g_cnt[t] > 100) ? 1.f : 0.f;   // MAX_VIEWS = 100, strict >
    if (t < NCLS) {
        float s = 0.f;
        for (int d = 0; d < DD; d++) { float m = g_means[t*DD + d]; s = fmaf(m, m, s); }
        sreg[t] = (s > 0.f) ? sqrtf(s) : 0.f;
    }
    if (t < NCLS*NCLS) {
        int a = t / NCLS, b2 = t % NCLS;
        float s = 0.f;
        for (int d = 0; d < DD; d++) {
            float diff = g_means[a*DD + d] - g_means[b2*DD + d];
            s = fmaf(diff, diff, s);
        }
        float pdn = (s > 0.f) ? sqrtf(s) : 0.f;
        float hd  = fmaxf(2.f*1.5f - pdn, 0.f);    // 2*DELTA_D
        spair[t] = hd*hd;
    }
    __syncthreads();
    if (t == 0) {
        int last = -1;
        for (int c = 0; c < NCLS; c++) if (vld[c] > 0.f) last = c;
        float tc = 0.f, lvar = 0.f, lreg = 0.f, ldist = 0.f;
        for (int c = 0; c < NCLS; c++) {
            if (vld[c] > 0.f) {
                tc   += 1.f;
                lvar += g_var[c] / fmaxf((float)g_cnt[c], 1.f);
                lreg += sreg[c];
            }
        }
        // faithful buggy double loop: a over all valid, b over valid except
        // the LAST valid class id; includes a == b pairs.
        for (int a = 0; a < NCLS; a++)
            for (int b2 = 0; b2 < NCLS; b2++)
                if (vld[a] > 0.f && vld[b2] > 0.f && b2 != last)
                    ldist += spair[a*NCLS + b2];
        out[0] = lvar/tc + ldist/(tc*(tc - 1.f)) + 0.001f*lreg/tc;  // ALPHA=BETA=1, GAMMA=1e-3
    }
}

// ---------------------------------------------------------------- launch
extern "C" void kernel_launch(void* const* d_in, const int* in_sizes, int n_in,
                              void* d_out, int out_size) {
    const float* feats  = (const float*)d_in[0];
    const int*   labels = (const int*)d_in[1];
    float* out = (float*)d_out;

    k_zero <<<(NCLS*DD + 255)/256, 256>>>();
    k_prep <<<NPIX/256, 256>>>(labels);
    k_pass1<<<dim3(32, 8, P1_SPLIT), P1_THREADS>>>(feats);
    k_means<<<(NCLS*DD + 255)/256, 256>>>();
    k_pass2<<<NPIX/1024, 256>>>(feats);
    k_final<<<1, 512>>>(out);
}

// round 4
// speedup vs baseline: 1.2961x; 1.2961x over previous
#include <cuda_runtime.h>
#include <math.h>

#define NCLS 19
#define DD   128
#define HWP  65536          // H*W
#define BB   8
#define NPIX (BB*HWP)       // 524288

#define PREP_BLOCKS (NPIX/256)          // 2048
#define P1_JQ      32
#define P1_SPLIT   4
#define P1_THREADS 128
#define P1_BLOCKS  (P1_JQ*BB*P1_SPLIT)  // 1024
#define P2_THREADS 256
#define P2_BLOCKS  (NPIX/4/P2_THREADS)  // 512

// ---- static scratch (no allocations allowed; zero-init at load) ----
__device__ float          g_sums[NCLS*DD];
__device__ float          g_means[NCLS*DD];
__device__ int            g_hist[PREP_BLOCKS*NCLS];
__device__ int            g_cnt[NCLS];
__device__ float          g_var[NCLS];
__device__ unsigned int   g_done1;
__device__ unsigned int   g_done2;
__device__ unsigned char  g_labs[NPIX];

// ------------------------------------------------------ label pack + hist
__global__ void __launch_bounds__(256) k_prep(const int* __restrict__ labels) {
    __shared__ int hist[NCLS];
    int t = threadIdx.x;
    if (t < NCLS) hist[t] = 0;
    __syncthreads();
    int p = blockIdx.x*256 + t;
    int lab = labels[p];
    unsigned char u = (lab >= 0 && lab < NCLS) ? (unsigned char)lab : (unsigned char)255;
    g_labs[p] = u;
    if (u < NCLS) atomicAdd(&hist[u], 1);
    __syncthreads();
    if (t < NCLS) g_hist[blockIdx.x*NCLS + t] = hist[t];
}

// ---------------------------------------------------------------- pass 1
// Each thread owns a fixed d-quad (d0..d0+3). One label test guards TWO
// packed f32x2 adds (4 elements). Explicit double-buffer prefetch.
// Last-arriving block reduces hist -> g_cnt, computes g_means, resets scratch.
__device__ __forceinline__ unsigned long long packf2(float lo, float hi) {
    unsigned long long v;
    asm("mov.b64 %0, {%1, %2};" : "=l"(v) : "f"(lo), "f"(hi));
    return v;
}

template<int CI>
__device__ __forceinline__ void step_all(unsigned long long* accA, unsigned long long* accB,
                                         unsigned long long vA, unsigned long long vB, int lab) {
    asm("{\n\t.reg .pred p;\n\t"
        "setp.eq.s32 p, %2, %3;\n\t"
        "@p add.rn.f32x2 %0, %0, %4;\n\t"
        "@p add.rn.f32x2 %1, %1, %5;\n\t}"
        : "+l"(accA[CI]), "+l"(accB[CI])
        : "r"(lab), "n"(CI), "l"(vA), "l"(vB));
    if constexpr (CI + 1 < NCLS) step_all<CI+1>(accA, accB, vA, vB, lab);
}

__global__ void __launch_bounds__(P1_THREADS) k_pass1(const float* __restrict__ feats) {
    int jq = blockIdx.x;            // d-quad index 0..31
    int b  = blockIdx.y;            // batch plane 0..7
    int s  = blockIdx.z;            // pixel split 0..3
    int d0 = jq * 4;
    const int nvec  = HWP / 4;          // 16384 float4 per plane
    const int chunk = nvec / P1_SPLIT;  // 4096
    const int base  = s * chunk;

    const float4* f0 = (const float4*)(feats + ((size_t)b*DD + d0    ) * HWP) + base;
    const float4* f1 = (const float4*)(feats + ((size_t)b*DD + d0 + 1) * HWP) + base;
    const float4* f2 = (const float4*)(feats + ((size_t)b*DD + d0 + 2) * HWP) + base;
    const float4* f3 = (const float4*)(feats + ((size_t)b*DD + d0 + 3) * HWP) + base;
    const uchar4* lb = (const uchar4*)(g_labs + (size_t)b*HWP) + base;

    unsigned long long accA[NCLS], accB[NCLS];
    #pragma unroll
    for (int c = 0; c < NCLS; c++) { accA[c] = 0ull; accB[c] = 0ull; }

    // double-buffered pixel loop: loads for i+stride issued before compute of i
    int i = threadIdx.x;
    float4 a0 = f0[i], a1 = f1[i], a2 = f2[i], a3 = f3[i];
    uchar4 l  = lb[i];
    while (true) {
        int j = i + P1_THREADS;
        float4 b0, b1, b2, b3; uchar4 m;
        bool more = (j < chunk);
        if (more) { b0 = f0[j]; b1 = f1[j]; b2 = f2[j]; b3 = f3[j]; m = lb[j]; }
        step_all<0>(accA, accB, packf2(a0.x, a1.x), packf2(a2.x, a3.x), (int)l.x);
        step_all<0>(accA, accB, packf2(a0.y, a1.y), packf2(a2.y, a3.y), (int)l.y);
        step_all<0>(accA, accB, packf2(a0.z, a1.z), packf2(a2.z, a3.z), (int)l.z);
        step_all<0>(accA, accB, packf2(a0.w, a1.w), packf2(a2.w, a3.w), (int)l.w);
        if (!more) break;
        a0 = b0; a1 = b1; a2 = b2; a3 = b3; l = m; i = j;
    }

    // block reduce: warp shuffle -> shared -> global atomics
    __shared__ float shred[NCLS*4];
    if (threadIdx.x < NCLS*4) shred[threadIdx.x] = 0.f;
    __syncthreads();
    int lane = threadIdx.x & 31;
    #pragma unroll
    for (int c = 0; c < NCLS; c++) {
        float x0, x1, x2, x3;
        asm("mov.b64 {%0, %1}, %2;" : "=f"(x0), "=f"(x1) : "l"(accA[c]));
        asm("mov.b64 {%0, %1}, %2;" : "=f"(x2), "=f"(x3) : "l"(accB[c]));
        #pragma unroll
        for (int o = 16; o; o >>= 1) {
            x0 += __shfl_down_sync(0xffffffffu, x0, o);
            x1 += __shfl_down_sync(0xffffffffu, x1, o);
            x2 += __shfl_down_sync(0xffffffffu, x2, o);
            x3 += __shfl_down_sync(0xffffffffu, x3, o);
        }
        if (lane == 0) {
            atomicAdd(&shred[c*4+0], x0);
            atomicAdd(&shred[c*4+1], x1);
            atomicAdd(&shred[c*4+2], x2);
            atomicAdd(&shred[c*4+3], x3);
        }
    }
    __syncthreads();
    if (threadIdx.x < NCLS*4) {
        int c = threadIdx.x >> 2, k = threadIdx.x & 3;
        atomicAdd(&g_sums[c*DD + d0 + k], shred[threadIdx.x]);
    }

    // ---- last-arriving block: counts, means, scratch reset ----
    __threadfence();
    __shared__ bool isLast;
    if (threadIdx.x == 0) {
        unsigned int v = atomicAdd(&g_done1, 1u);
        isLast = (v == P1_BLOCKS - 1);
    }
    __syncthreads();
    if (!isLast) return;

    __shared__ int scnt[NCLS];
    if (threadIdx.x < NCLS) scnt[threadIdx.x] = 0;
    __syncthreads();
    {
        const int R = PREP_BLOCKS / P1_THREADS;   // 16 rows per thread
        int loc[NCLS];
        #pragma unroll
        for (int c = 0; c < NCLS; c++) loc[c] = 0;
        const int* rows = &g_hist[threadIdx.x * R * NCLS];
        for (int r = 0; r < R; r++) {
            #pragma unroll
            for (int c = 0; c < NCLS; c++) loc[c] += rows[r*NCLS + c];
        }
        #pragma unroll
        for (int c = 0; c < NCLS; c++) atomicAdd(&scnt[c], loc[c]);
    }
    __syncthreads();
    if (threadIdx.x < NCLS) g_cnt[threadIdx.x] = scnt[threadIdx.x];
    for (int idx = threadIdx.x; idx < NCLS*DD; idx += P1_THREADS) {
        int c = idx >> 7;
        g_means[idx] = g_sums[idx] / fmaxf((float)scnt[c], 1.f);
        g_sums[idx] = 0.f;                       // reset for next replay
    }
    if (threadIdx.x < NCLS) g_var[threadIdx.x] = 0.f;
    if (threadIdx.x == 0) { g_done1 = 0u; g_done2 = 0u; }
}

// ---------------------------------------------------------------- pass 2
// 4 pixels/thread via float4; means in shared at stride 129 (conflict-free).
// Last-arriving block assembles the final loss and writes out[0].
__global__ void __launch_bounds__(P2_THREADS) k_pass2(const float* __restrict__ feats,
                                                      float* __restrict__ out) {
    __shared__ float ms[NCLS*129];
    __shared__ float vs[NCLS];
    int t = threadIdx.x;
    for (int i = t; i < NCLS*DD; i += P2_THREADS)
        ms[(i >> 7)*129 + (i & 127)] = g_means[i];
    if (t < NCLS) vs[t] = 0.f;
    __syncthreads();

    int q  = blockIdx.x*P2_THREADS + t;   // pixel-quad index
    int b  = q >> 14;                     // 16384 quads per batch plane
    int hq = q & 16383;
    const float4* fp = (const float4*)(feats + (size_t)b*DD*HWP) + hq;
    uchar4 l = ((const uchar4*)g_labs)[q];

    int l0 = l.x, l1 = l.y, l2 = l.z, l3 = l.w;
    const float* m0 = ms + (l0 < NCLS ? l0 : 0)*129;
    const float* m1 = ms + (l1 < NCLS ? l1 : 0)*129;
    const float* m2 = ms + (l2 < NCLS ? l2 : 0)*129;
    const float* m3 = ms + (l3 < NCLS ? l3 : 0)*129;

    float acc0 = 0.f, acc1 = 0.f, acc2 = 0.f, acc3 = 0.f;
    #pragma unroll 8
    for (int d = 0; d < DD; d++) {
        float4 v = fp[(size_t)d * (HWP/4)];
        float df;
        df = v.x - m0[d]; acc0 = fmaf(df, df, acc0);
        df = v.y - m1[d]; acc1 = fmaf(df, df, acc1);
        df = v.z - m2[d]; acc2 = fmaf(df, df, acc2);
        df = v.w - m3[d]; acc3 = fmaf(df, df, acc3);
    }
    if (l0 < NCLS) { float h = fmaxf(sqrtf(acc0) - 0.5f, 0.f); atomicAdd(&vs[l0], h*h); }
    if (l1 < NCLS) { float h = fmaxf(sqrtf(acc1) - 0.5f, 0.f); atomicAdd(&vs[l1], h*h); }
    if (l2 < NCLS) { float h = fmaxf(sqrtf(acc2) - 0.5f, 0.f); atomicAdd(&vs[l2], h*h); }
    if (l3 < NCLS) { float h = fmaxf(sqrtf(acc3) - 0.5f, 0.f); atomicAdd(&vs[l3], h*h); }
    __syncthreads();
    if (t < NCLS) atomicAdd(&g_var[t], vs[t]);

    // ---- last-arriving block: final loss assembly ----
    __threadfence();
    __shared__ bool isLast;
    if (t == 0) {
        unsigned int v = atomicAdd(&g_done2, 1u);
        isLast = (v == P2_BLOCKS - 1);
    }
    __syncthreads();
    if (!isLast) return;

    __shared__ float vld[NCLS];
    __shared__ float sreg[NCLS];
    __shared__ float spair[NCLS*NCLS];
    if (t < NCLS) {
        vld[t] = (g_cnt[t] > 100) ? 1.f : 0.f;   // MAX_VIEWS = 100, strict >
        float s = 0.f;
        #pragma unroll 16
        for (int d = 0; d < DD; d++) { float m = ms[t*129 + d]; s = fmaf(m, m, s); }
        sreg[t] = (s > 0.f) ? sqrtf(s) : 0.f;
    }
    for (int idx = t; idx < NCLS*NCLS; idx += P2_THREADS) {
        int a = idx / NCLS, b2 = idx % NCLS;
        float s = 0.f;
        #pragma unroll 16
        for (int d = 0; d < DD; d++) {
            float diff = ms[a*129 + d] - ms[b2*129 + d];
            s = fmaf(diff, diff, s);
        }
        float pdn = (s > 0.f) ? sqrtf(s) : 0.f;
        float hd  = fmaxf(2.f*1.5f - pdn, 0.f);   // 2*DELTA_D
        spair[idx] = hd*hd;
    }
    __syncthreads();
    if (t == 0) {
        int last = -1;
        for (int c = 0; c < NCLS; c++) if (vld[c] > 0.f) last = c;
        float tc = 0.f, lvar = 0.f, lreg = 0.f, ldist = 0.f;
        for (int c = 0; c < NCLS; c++) {
            if (vld[c] > 0.f) {
                tc   += 1.f;
                lvar += g_var[c] / fmaxf((float)g_cnt[c], 1.f);
                lreg += sreg[c];
            }
        }
        // faithful buggy double loop: a over all valid, b over valid except
        // the LAST valid class id; includes a == b pairs.
        for (int a = 0; a < NCLS; a++)
            for (int b2 = 0; b2 < NCLS; b2++)
                if (vld[a] > 0.f && vld[b2] > 0.f && b2 != last)
                    ldist += spair[a*NCLS + b2];
        out[0] = lvar/tc + ldist/(tc*(tc - 1.f)) + 0.001f*lreg/tc;  // ALPHA=BETA=1, GAMMA=1e-3
        g_done2 = 0u;                             // reset for next replay
    }
}

// ---------------------------------------------------------------- launch
extern "C" void kernel_launch(void* const* d_in, const int* in_sizes, int n_in,
                              void* d_out, int out_size) {
    const float* feats  = (const float*)d_in[0];
    const int*   labels = (const int*)d_in[1];
    float* out = (float*)d_out;

    k_prep <<<PREP_BLOCKS, 256>>>(labels);
    k_pass1<<<dim3(P1_JQ, BB, P1_SPLIT), P1_THREADS>>>(feats);
    k_pass2<<<P2_BLOCKS, P2_THREADS>>>(feats, out);
}